// round 7
// baseline (speedup 1.0000x reference)
#include <cuda_runtime.h>
#include <cstdint>

#define S 64
#define P 2048
#define C 32
#define A 2048
#define D 128
#define E 64
#define E2 32

#define SPLITS 16
#define PH (P / SPLITS)   // 128 pixels per block
#define NW 8              // warps per k_attn block

typedef unsigned long long ull;

__device__ __forceinline__ ull pack2(float lo, float hi) {
    ull r; asm("mov.b64 %0,{%1,%2};" : "=l"(r) : "f"(lo), "f"(hi)); return r;
}
__device__ __forceinline__ void unpack2(ull v, float& lo, float& hi) {
    asm("mov.b64 {%0,%1},%2;" : "=f"(lo), "=f"(hi) : "l"(v));
}
__device__ __forceinline__ ull fma2(ull a, ull b, ull c) {
    ull d; asm("fma.rn.f32x2 %0,%1,%2,%3;" : "=l"(d) : "l"(a), "l"(b), "l"(c)); return d;
}
__device__ __forceinline__ ull add2(ull a, ull b) {
    ull d; asm("add.rn.f32x2 %0,%1,%2;" : "=l"(d) : "l"(a), "l"(b)); return d;
}
__device__ __forceinline__ ull mul2(ull a, ull b) {
    ull d; asm("mul.rn.f32x2 %0,%1,%2;" : "=l"(d) : "l"(a), "l"(b)); return d;
}
__device__ __forceinline__ ull relu2(ull v) {
    float lo, hi; unpack2(v, lo, hi);
    return pack2(fmaxf(lo, 0.f), fmaxf(hi, 0.f));
}

// ------------------------- global scratch -------------------------
__device__ ull   g_att2u[A * E2];
__device__ int   g_alist[S * A];
__device__ int   g_cnt[S];
__device__ float g_pm[A * SPLITS];
__device__ float g_pl[A * SPLITS];
__device__ ull   g_paccu[A * SPLITS * (C / 2)];

// ---------------------------------------------------------------------------
// k_prep: blocks [0,S): per-scene agent lists (ballot compaction).
//         blocks [S, S+A/8): att2[a] = b_df + dyn[a] @ W_df (8 agents/block).
// ---------------------------------------------------------------------------
__global__ __launch_bounds__(256) void k_prep(const int* __restrict__ sidx,
                                              const float* __restrict__ dyn,
                                              const float* __restrict__ Wdf,
                                              const float* __restrict__ bdf) {
    __shared__ ull Wp2[D * E2];      // 32 KB (att2 role)
    __shared__ ull dyn2[8 * D];      // 8 KB pre-packed (d,d) pairs
    __shared__ int wcnt[8];          // group role

    const int tid = threadIdx.x, wid = tid >> 5, lane = tid & 31;

    if (blockIdx.x < S) {
        int s = blockIdx.x;
        int base = 0;
#pragma unroll
        for (int r = 0; r < A / 256; r++) {
            int a = r * 256 + tid;
            bool p = (sidx[a] == s);
            unsigned bal = __ballot_sync(0xffffffffu, p);
            if (lane == 0) wcnt[wid] = __popc(bal);
            __syncthreads();
            int woff = 0, tot = 0;
#pragma unroll
            for (int w = 0; w < 8; w++) {
                int c = wcnt[w]; if (w < wid) woff += c; tot += c;
            }
            if (p) g_alist[s * A + base + woff + __popc(bal & ((1u << lane) - 1u))] = a;
            base += tot;
            __syncthreads();
        }
        if (tid == 0) g_cnt[s] = base;
        return;
    }

    const int a0 = (blockIdx.x - S) * 8;
    const ull* Wsrc = (const ull*)Wdf;
    for (int i = tid; i < D * E2; i += 256) Wp2[i] = Wsrc[i];
    {
        float4 v = ((const float4*)(dyn + (size_t)a0 * D))[tid];
        dyn2[tid * 4 + 0] = pack2(v.x, v.x);
        dyn2[tid * 4 + 1] = pack2(v.y, v.y);
        dyn2[tid * 4 + 2] = pack2(v.z, v.z);
        dyn2[tid * 4 + 3] = pack2(v.w, v.w);
    }
    __syncthreads();

    const int aa = tid >> 5, e2 = tid & 31;
    ull acc0 = ((const ull*)bdf)[e2], acc1 = 0, acc2 = 0, acc3 = 0;
    const ull* dr = dyn2 + aa * D;
#pragma unroll 8
    for (int c = 0; c < D; c += 4) {
        acc0 = fma2(dr[c + 0], Wp2[(c + 0) * E2 + e2], acc0);
        acc1 = fma2(dr[c + 1], Wp2[(c + 1) * E2 + e2], acc1);
        acc2 = fma2(dr[c + 2], Wp2[(c + 2) * E2 + e2], acc2);
        acc3 = fma2(dr[c + 3], Wp2[(c + 3) * E2 + e2], acc3);
    }
    g_att2u[(size_t)(a0 + aa) * E2 + e2] = add2(add2(acc0, acc1), add2(acc2, acc3));
}

// ---------------------------------------------------------------------------
// k_attn — block = (scene, sixteenth of P, chunk slot). 256 threads / 8 warps.
// lane = agent (32-agent chunk), warp = 16-pixel slice of the 128 pixels.
// Merge buffer overlays att1s (dead after logit phase) -> 69.4 KB smem,
// 3 blocks/SM. b_fc dropped (softmax-invariant).
// ---------------------------------------------------------------------------
// smem layout (bytes, 16-aligned)
#define OFF_ATT1S 0                  // ull[128*34] = 34816 ; merge overlay [8][17][32]
#define OFF_GSS   34816              // ull[128*16] = 16384
#define OFF_ATT2T 51200              // ull[32*33]  = 8448
#define OFF_COEF  59648              // float[8*32] = 1024
#define OFF_WP    60672              // ull[32*32]  = 8192
#define OFF_WFC   68864              // ull[32]     = 256
#define OFF_BSN   69120              // ull[32]     = 256
#define SMEM_ATTN 69376

__global__ __launch_bounds__(256, 3) void k_attn(const float* __restrict__ gs,
                                                 const float* __restrict__ wfc,
                                                 const float* __restrict__ Wsn,
                                                 const float* __restrict__ bsn) {
    extern __shared__ __align__(16) char smraw[];
    ull*   att1s = (ull*)(smraw + OFF_ATT1S);   // [px][34] (32 e-pairs + pad)
    ull*   gss   = (ull*)(smraw + OFF_GSS);     // [px][16 c-pairs]
    ull*   att2T = (ull*)(smraw + OFF_ATT2T);   // [e2][33]
    float* coef  = (float*)(smraw + OFF_COEF);  // [8][32]
    ull*   Wp    = (ull*)(smraw + OFF_WP);      // [c][32 e-pairs]
    ull*   wfcp  = (ull*)(smraw + OFF_WFC);
    ull*   bsnp  = (ull*)(smraw + OFF_BSN);
    ull*   mbuf  = att1s;                        // overlay: [j=warp][17][32]

    const int tid = threadIdx.x, wid = tid >> 5, lane = tid & 31;
    const int sblk = blockIdx.x >> 5;
    const int part = (blockIdx.x >> 1) & 15;
    const int slot = blockIdx.x & 1;
    const int p0 = part * PH;
    const int nA = g_cnt[sblk];
    if (slot * 32 >= nA) return;

    // stage weights once
    {
        const ull* Wsrc = (const ull*)Wsn;
        for (int i = tid; i < C * E2; i += 256) Wp[i] = Wsrc[i];
        if (tid < E2) {
            wfcp[tid] = ((const ull*)wfc)[tid];
            bsnp[tid] = ((const ull*)bsn)[tid];
        }
    }
    __syncthreads();

    const int* alist = g_alist + sblk * A;
    const int pbase = wid * 16;

    for (int c0 = slot * 32; c0 < nA; c0 += 64) {
        // ---- stage att2 (transposed [e2][slot]) ----
        for (int idx = tid; idx < 32 * E2; idx += 256) {
            int j = idx >> 5, e2 = idx & 31;
            int src = c0 + j; if (src >= nA) src = nA - 1;
            att2T[e2 * 33 + j] = g_att2u[(size_t)alist[src] * E2 + e2];
        }
        // ---- prologue: att1 for 128 pixels; gss verbatim copy ----
        {
            const int px = tid >> 1, half = tid & 1;
            const float4* gr = (const float4*)(gs + (size_t)(sblk * P + p0 + px) * C);
            float4 v4[8];
#pragma unroll
            for (int j = 0; j < 8; j++) v4[j] = gr[j];
            if (half == 0) {
                float4* gd = (float4*)(gss + px * 16);
#pragma unroll
                for (int j = 0; j < 8; j++) gd[j] = v4[j];   // bit-identical to pairs
            }
            float g[32];
#pragma unroll
            for (int j = 0; j < 8; j++) {
                g[4 * j] = v4[j].x; g[4 * j + 1] = v4[j].y;
                g[4 * j + 2] = v4[j].z; g[4 * j + 3] = v4[j].w;
            }
            ull acc[16];
#pragma unroll
            for (int k = 0; k < 16; k++) acc[k] = bsnp[half * 16 + k];
#pragma unroll 4
            for (int c = 0; c < C; c++) {
                ull gg = pack2(g[c], g[c]);
#pragma unroll
                for (int k = 0; k < 16; k++)
                    acc[k] = fma2(gg, Wp[c * E2 + half * 16 + k], acc[k]);
            }
            ulonglong2* dst = (ulonglong2*)(att1s + px * 34 + half * 16);
#pragma unroll
            for (int k = 0; k < 8; k++) {
                ulonglong2 v2; v2.x = acc[2 * k]; v2.y = acc[2 * k + 1];
                dst[k] = v2;
            }
        }
        __syncthreads();   // att1s, gss, att2T visible

        // ---- logits: 16 pixels x 32 lane-agents ----
        ull lg[16];
#pragma unroll
        for (int i = 0; i < 16; i++) lg[i] = 0ull;
#pragma unroll 2
        for (int e2 = 0; e2 < E2; e2 += 2) {
            ull wv0 = wfcp[e2], wv1 = wfcp[e2 + 1];
            ull bv0 = att2T[e2 * 33 + lane], bv1 = att2T[(e2 + 1) * 33 + lane];
            const ulonglong2* a1 = (const ulonglong2*)(att1s + pbase * 34 + e2);
#pragma unroll
            for (int i = 0; i < 16; i++) {
                ulonglong2 av = a1[i * 17];
                lg[i] = fma2(relu2(add2(av.x, bv0)), wv0, lg[i]);
                lg[i] = fma2(relu2(add2(av.y, bv1)), wv1, lg[i]);
            }
        }
        // ---- single-shot softmax over this warp's 16 pixels ----
        float ls[16];
#pragma unroll
        for (int i = 0; i < 16; i++) {
            float lo, hi; unpack2(lg[i], lo, hi);
            ls[i] = lo + hi;
        }
        float t8[8];
#pragma unroll
        for (int i = 0; i < 8; i++) t8[i] = fmaxf(ls[i], ls[i + 8]);
        float m = fmaxf(fmaxf(fmaxf(t8[0], t8[4]), fmaxf(t8[1], t8[5])),
                        fmaxf(fmaxf(t8[2], t8[6]), fmaxf(t8[3], t8[7])));
        float l0 = 0.f, l1 = 0.f;
        ull acc[16];
#pragma unroll
        for (int k = 0; k < 16; k++) acc[k] = 0ull;
#pragma unroll 4
        for (int i = 0; i < 16; i++) {
            float w = __expf(ls[i] - m);
            if (i & 1) l1 += w; else l0 += w;
            ull w2 = pack2(w, w);
            const ulonglong2* grw = (const ulonglong2*)(gss + (pbase + i) * 16);
#pragma unroll
            for (int k = 0; k < 8; k++) {
                ulonglong2 gv = grw[k];
                acc[2 * k]     = fma2(w2, gv.x, acc[2 * k]);
                acc[2 * k + 1] = fma2(w2, gv.y, acc[2 * k + 1]);
            }
        }
        float l = l0 + l1;

        __syncthreads();   // all warps done reading att1s/gss -> overlay OK

        // ---- merge: write states into mbuf (att1s overlay) ----
        {
            ull* dst = mbuf + (size_t)wid * 17 * 32;
#pragma unroll
            for (int k = 0; k < 16; k++) dst[k * 32 + lane] = acc[k];
            dst[16 * 32 + lane] = pack2(m, l);
        }
        __syncthreads();

        const int aidx = c0 + lane;
        const bool valid = (aidx < nA);

        if (wid == 0) {
            // per lane: merge 8 (m,l), emit coefficients
            float mj[8], lj[8];
#pragma unroll
            for (int j = 0; j < 8; j++)
                unpack2(mbuf[(size_t)j * 17 * 32 + 16 * 32 + lane], mj[j], lj[j]);
            float M = mj[0];
#pragma unroll
            for (int j = 1; j < 8; j++) M = fmaxf(M, mj[j]);
            float L = 0.f;
#pragma unroll
            for (int j = 0; j < 8; j++) {
                float cj = __expf(mj[j] - M);
                coef[j * 32 + lane] = cj;
                L += lj[j] * cj;
            }
            if (valid) {
                int a = alist[aidx];
                g_pm[(size_t)a * SPLITS + part] = M;
                g_pl[(size_t)a * SPLITS + part] = L;
            }
        }
        __syncthreads();

        // ---- all 8 warps: weighted k-sums, direct store ----
        {
            int k0 = wid * 2;
            ull s0 = 0ull, s1 = 0ull;
#pragma unroll
            for (int j = 0; j < 8; j++) {
                float cj = coef[j * 32 + lane];
                ull c2 = pack2(cj, cj);
                const ull* src = mbuf + (size_t)j * 17 * 32;
                s0 = fma2(src[k0 * 32 + lane], c2, s0);
                s1 = fma2(src[(k0 + 1) * 32 + lane], c2, s1);
            }
            if (valid) {
                int a = alist[aidx];
                size_t base = ((size_t)a * SPLITS + part) * 16;
                g_paccu[base + k0] = s0;
                g_paccu[base + k0 + 1] = s1;
            }
        }
        if (c0 + 64 < nA) __syncthreads();   // rare multi-chunk path
    }
}

// ---------------------------------------------------------------------------
// combine SPLITS partial softmax states per agent
// ---------------------------------------------------------------------------
__global__ __launch_bounds__(256) void k_combine(float* __restrict__ out) {
    int gw = (blockIdx.x * blockDim.x + threadIdx.x) >> 5;
    int lane = threadIdx.x & 31;
    if (gw >= A) return;
    int a = gw;
    float mm[SPLITS], llv[SPLITS];
    float M = -1e30f;
#pragma unroll
    for (int k = 0; k < SPLITS; k++) {
        mm[k] = g_pm[a * SPLITS + k];
        llv[k] = g_pl[a * SPLITS + k];
        M = fmaxf(M, mm[k]);
    }
    const float* gp = (const float*)g_paccu;
    float L = 0.f, v = 0.f;
#pragma unroll
    for (int k = 0; k < SPLITS; k++) {
        float sk = __expf(mm[k] - M);
        L += llv[k] * sk;
        v += gp[(size_t)(a * SPLITS + k) * C + lane] * sk;
    }
    out[a * C + lane] = v / L;
}

// ---------------------------------------------------------------------------
extern "C" void kernel_launch(void* const* d_in, const int* in_sizes, int n_in,
                              void* d_out, int out_size) {
    const float* gs   = (const float*)d_in[0];
    const int*   sidx = (const int*)d_in[1];
    const float* dyn  = (const float*)d_in[2];
    const float* Wsn  = (const float*)d_in[3];
    const float* bsn  = (const float*)d_in[4];
    const float* Wdf  = (const float*)d_in[5];
    const float* bdf  = (const float*)d_in[6];
    const float* wfc  = (const float*)d_in[7];
    float* out = (float*)d_out;

    k_prep<<<S + A / 8, 256>>>(sidx, dyn, Wdf, bdf);

    cudaFuncSetAttribute(k_attn, cudaFuncAttributeMaxDynamicSharedMemorySize,
                         SMEM_ATTN);
    k_attn<<<S * SPLITS * 2, 256, SMEM_ATTN>>>(gs, wfc, Wsn, bsn);

    k_combine<<<(A * 32) / 256, 256>>>(out);
}

// round 10
// speedup vs baseline: 1.2247x; 1.2247x over previous
#include <cuda_runtime.h>
#include <cstdint>

#define S 64
#define P 2048
#define C 32
#define A 2048
#define D 128
#define E 64
#define E2 32

#define SPLITS 16
#define PH (P / SPLITS)   // 128 pixels per block

typedef unsigned long long ull;

__device__ __forceinline__ ull pack2(float lo, float hi) {
    ull r; asm("mov.b64 %0,{%1,%2};" : "=l"(r) : "f"(lo), "f"(hi)); return r;
}
__device__ __forceinline__ void unpack2(ull v, float& lo, float& hi) {
    asm("mov.b64 {%0,%1},%2;" : "=f"(lo), "=f"(hi) : "l"(v));
}
__device__ __forceinline__ ull fma2(ull a, ull b, ull c) {
    ull d; asm("fma.rn.f32x2 %0,%1,%2,%3;" : "=l"(d) : "l"(a), "l"(b), "l"(c)); return d;
}
__device__ __forceinline__ ull add2(ull a, ull b) {
    ull d; asm("add.rn.f32x2 %0,%1,%2;" : "=l"(d) : "l"(a), "l"(b)); return d;
}
__device__ __forceinline__ ull relu2(ull v) {
    float lo, hi; unpack2(v, lo, hi);
    return pack2(fmaxf(lo, 0.f), fmaxf(hi, 0.f));
}

// ------------------------- global scratch -------------------------
__device__ ull   g_att2u[A * E2];
__device__ int   g_alist[S * A];
__device__ int   g_cnt[S];
__device__ float g_pm[A * SPLITS];
__device__ float g_pl[A * SPLITS];
__device__ ull   g_paccu[A * SPLITS * (C / 2)];

// ---------------------------------------------------------------------------
// k_prep: blocks [0,S): per-scene agent lists (2-sync ballot compaction).
//         blocks [S, S+A/32): att2 for 32 agents (dyn smem: W 32K + dyn 16K).
// ---------------------------------------------------------------------------
#define PREP_SMEM 49152
__global__ __launch_bounds__(256) void k_prep(const int* __restrict__ sidx,
                                              const float* __restrict__ dyn,
                                              const float* __restrict__ Wdf,
                                              const float* __restrict__ bdf) {
    extern __shared__ __align__(16) char dsm[];
    __shared__ int cnt8[64];   // [round][warp]

    const int tid = threadIdx.x, wid = tid >> 5, lane = tid & 31;

    if (blockIdx.x < S) {
        // ---- group role ----
        const int s = blockIdx.x;
        unsigned pm = 0;
        int rank[8];
#pragma unroll
        for (int r = 0; r < 8; r++) {
            int a = r * 256 + tid;
            bool p = (sidx[a] == s);
            unsigned bal = __ballot_sync(0xffffffffu, p);
            if (lane == 0) cnt8[r * 8 + wid] = __popc(bal);
            if (p) pm |= (1u << r);
            rank[r] = __popc(bal & ((1u << lane) - 1u));
        }
        __syncthreads();
        int run = 0, off[8];
#pragma unroll
        for (int r = 0; r < 8; r++) {
            int woff = 0, tot = 0;
#pragma unroll
            for (int w = 0; w < 8; w++) {
                int c = cnt8[r * 8 + w];
                if (w < wid) woff += c;
                tot += c;
            }
            off[r] = run + woff;
            run += tot;
        }
#pragma unroll
        for (int r = 0; r < 8; r++)
            if ((pm >> r) & 1)
                g_alist[s * A + off[r] + rank[r]] = r * 256 + tid;
        if (tid == 0) g_cnt[s] = run;
        return;
    }

    // ---- att2 role: 32 agents, 4 per warp (i indexes AGENTS) ----
    ull*   Wp2   = (ull*)dsm;                 // [128][32] = 32 KB
    float* dyn_s = (float*)(dsm + 32768);     // [32][128] = 16 KB
    const int a0 = (blockIdx.x - S) * 32;
    {
        const ull* Wsrc = (const ull*)Wdf;
#pragma unroll
        for (int k = 0; k < 16; k++) Wp2[tid + k * 256] = Wsrc[tid + k * 256];
        const float4* dsrc = (const float4*)(dyn + (size_t)a0 * D);
        float4* ddst = (float4*)dyn_s;
#pragma unroll
        for (int k = 0; k < 4; k++) ddst[tid + k * 256] = dsrc[tid + k * 256];
    }
    __syncthreads();

    ull acc[4];
    ull b0 = ((const ull*)bdf)[lane];
#pragma unroll
    for (int i = 0; i < 4; i++) acc[i] = b0;   // FIX: every agent gets the bias
    const float* dr = dyn_s + (wid * 4) * D;
#pragma unroll 4
    for (int c = 0; c < D; c++) {
        ull w2 = Wp2[c * 32 + lane];
#pragma unroll
        for (int i = 0; i < 4; i++) {
            float d = dr[i * D + c];
            acc[i] = fma2(pack2(d, d), w2, acc[i]);
        }
    }
#pragma unroll
    for (int i = 0; i < 4; i++)
        g_att2u[(size_t)(a0 + wid * 4 + i) * E2 + lane] = acc[i];
}

// ---------------------------------------------------------------------------
// k_attn — block = (scene, sixteenth of P). 256 threads / 8 warps, 2 blk/SM.
// lane = agent (32-agent chunks), warp = 16-pixel slice of 128 pixels.
// Coefficient-based merge: 3 syncs/chunk. b_fc dropped (softmax-invariant).
// ---------------------------------------------------------------------------
// smem layout (bytes)
#define OFF_ATT1S 0                  // ull[128*34] = 34816
#define OFF_GSS   34816              // ull[128*16] = 16384
#define OFF_ATT2T 51200              // ull[32*33]  = 8448
#define OFF_COEF  59648              // float[8*32] = 1024
#define OFF_WP    60672              // ull[32*32]  = 8192
#define OFF_MBUF  68864              // ull[8*17*32]= 34816
#define OFF_WFC   103680             // ull[32]     = 256
#define OFF_BSN   103936             // ull[32]     = 256
#define SMEM_ATTN 104192

__global__ __launch_bounds__(256, 2) void k_attn(const float* __restrict__ gs,
                                                 const float* __restrict__ wfc,
                                                 const float* __restrict__ Wsn,
                                                 const float* __restrict__ bsn) {
    extern __shared__ __align__(16) char smraw[];
    ull*   att1s = (ull*)(smraw + OFF_ATT1S);   // [px][34]
    ull*   gss   = (ull*)(smraw + OFF_GSS);     // [px][16]
    ull*   att2T = (ull*)(smraw + OFF_ATT2T);   // [e2][33]
    float* coef  = (float*)(smraw + OFF_COEF);  // [8][32]
    ull*   Wp    = (ull*)(smraw + OFF_WP);      // [c][32]
    ull*   mbuf  = (ull*)(smraw + OFF_MBUF);    // [8][17][32]
    ull*   wfcp  = (ull*)(smraw + OFF_WFC);
    ull*   bsnp  = (ull*)(smraw + OFF_BSN);

    const int tid = threadIdx.x, wid = tid >> 5, lane = tid & 31;
    const int sblk = blockIdx.x >> 4;
    const int part = blockIdx.x & 15;
    const int p0 = part * PH;
    const int nA = g_cnt[sblk];
    if (nA == 0) return;

    // ---- stage weights ----
    {
        const ull* Wsrc = (const ull*)Wsn;
        for (int i = tid; i < C * E2; i += 256) Wp[i] = Wsrc[i];
        if (tid < E2) {
            wfcp[tid] = ((const ull*)wfc)[tid];
            bsnp[tid] = ((const ull*)bsn)[tid];
        }
    }
    __syncthreads();

    // ---- prologue: att1 for 128 pixels; gss verbatim copy ----
    {
        const int px = tid >> 1, half = tid & 1;
        const float4* gr = (const float4*)(gs + (size_t)(sblk * P + p0 + px) * C);
        float4 v4[8];
#pragma unroll
        for (int j = 0; j < 8; j++) v4[j] = gr[j];
        if (half == 0) {
            float4* gd = (float4*)(gss + px * 16);
#pragma unroll
            for (int j = 0; j < 8; j++) gd[j] = v4[j];
        }
        float g[32];
#pragma unroll
        for (int j = 0; j < 8; j++) {
            g[4 * j] = v4[j].x; g[4 * j + 1] = v4[j].y;
            g[4 * j + 2] = v4[j].z; g[4 * j + 3] = v4[j].w;
        }
        ull acc[16];
#pragma unroll
        for (int k = 0; k < 16; k++) acc[k] = bsnp[half * 16 + k];
#pragma unroll 4
        for (int c = 0; c < C; c++) {
            ull gg = pack2(g[c], g[c]);
#pragma unroll
            for (int k = 0; k < 16; k++)
                acc[k] = fma2(gg, Wp[c * E2 + half * 16 + k], acc[k]);
        }
        ulonglong2* dst = (ulonglong2*)(att1s + px * 34 + half * 16);
#pragma unroll
        for (int k = 0; k < 8; k++) {
            ulonglong2 v2; v2.x = acc[2 * k]; v2.y = acc[2 * k + 1];
            dst[k] = v2;
        }
    }
    __syncthreads();   // att1s/gss visible

    const int* alist = g_alist + sblk * A;
    const int pbase = wid * 16;

    for (int c0 = 0; c0 < nA; c0 += 32) {
        // ---- stage att2 (transposed [e2][slot]) ----
        for (int idx = tid; idx < 32 * E2; idx += 256) {
            int j = idx >> 5, e2 = idx & 31;
            int src = c0 + j; if (src >= nA) src = nA - 1;
            att2T[e2 * 33 + j] = g_att2u[(size_t)alist[src] * E2 + e2];
        }
        __syncthreads();   // (1) att2T ready; prior chunk's ksum also done

        // ---- logits: 16 pixels x 32 lane-agents ----
        ull lg[16];
#pragma unroll
        for (int i = 0; i < 16; i++) lg[i] = 0ull;
#pragma unroll 2
        for (int e2 = 0; e2 < E2; e2 += 2) {
            ull wv0 = wfcp[e2], wv1 = wfcp[e2 + 1];
            ull bv0 = att2T[e2 * 33 + lane], bv1 = att2T[(e2 + 1) * 33 + lane];
            const ulonglong2* a1 = (const ulonglong2*)(att1s + pbase * 34 + e2);
#pragma unroll
            for (int i = 0; i < 16; i++) {
                ulonglong2 av = a1[i * 17];
                lg[i] = fma2(relu2(add2(av.x, bv0)), wv0, lg[i]);
                lg[i] = fma2(relu2(add2(av.y, bv1)), wv1, lg[i]);
            }
        }
        // ---- single-shot softmax over this warp's 16 pixels ----
        float ls[16];
#pragma unroll
        for (int i = 0; i < 16; i++) {
            float lo, hi; unpack2(lg[i], lo, hi);
            ls[i] = lo + hi;
        }
        float t8[8];
#pragma unroll
        for (int i = 0; i < 8; i++) t8[i] = fmaxf(ls[i], ls[i + 8]);
        float m = fmaxf(fmaxf(fmaxf(t8[0], t8[4]), fmaxf(t8[1], t8[5])),
                        fmaxf(fmaxf(t8[2], t8[6]), fmaxf(t8[3], t8[7])));
        float l0 = 0.f, l1 = 0.f;
        ull acc[16];
#pragma unroll
        for (int k = 0; k < 16; k++) acc[k] = 0ull;
#pragma unroll 4
        for (int i = 0; i < 16; i++) {
            float w = __expf(ls[i] - m);
            if (i & 1) l1 += w; else l0 += w;
            ull w2 = pack2(w, w);
            const ulonglong2* grw = (const ulonglong2*)(gss + (pbase + i) * 16);
#pragma unroll
            for (int k = 0; k < 8; k++) {
                ulonglong2 gv = grw[k];
                acc[2 * k]     = fma2(w2, gv.x, acc[2 * k]);
                acc[2 * k + 1] = fma2(w2, gv.y, acc[2 * k + 1]);
            }
        }
        float l = l0 + l1;

        // ---- dump all 8 warp-states ----
        {
            ull* dst = mbuf + (size_t)wid * 17 * 32;
#pragma unroll
            for (int k = 0; k < 16; k++) dst[k * 32 + lane] = acc[k];
            dst[16 * 32 + lane] = pack2(m, l);
        }
        __syncthreads();   // (2) states visible

        const int aidx = c0 + lane;
        const bool valid = (aidx < nA);

        if (wid == 0) {
            float mj[8], lj[8];
#pragma unroll
            for (int j = 0; j < 8; j++)
                unpack2(mbuf[(size_t)j * 17 * 32 + 16 * 32 + lane], mj[j], lj[j]);
            float M = mj[0];
#pragma unroll
            for (int j = 1; j < 8; j++) M = fmaxf(M, mj[j]);
            float L = 0.f;
#pragma unroll
            for (int j = 0; j < 8; j++) {
                float cj = __expf(mj[j] - M);
                coef[j * 32 + lane] = cj;
                L += lj[j] * cj;
            }
            if (valid) {
                int a = alist[aidx];
                g_pm[(size_t)a * SPLITS + part] = M;
                g_pl[(size_t)a * SPLITS + part] = L;
            }
        }
        __syncthreads();   // (3) coefs visible

        // ---- all 8 warps: weighted k-sums, direct gmem store ----
        {
            const int k0 = wid * 2;
            ull s0 = 0ull, s1 = 0ull;
#pragma unroll
            for (int j = 0; j < 8; j++) {
                float cj = coef[j * 32 + lane];
                ull c2 = pack2(cj, cj);
                const ull* src = mbuf + (size_t)j * 17 * 32;
                s0 = fma2(src[k0 * 32 + lane], c2, s0);
                s1 = fma2(src[(k0 + 1) * 32 + lane], c2, s1);
            }
            if (valid) {
                int a = alist[aidx];
                size_t base = ((size_t)a * SPLITS + part) * 16;
                g_paccu[base + k0] = s0;
                g_paccu[base + k0 + 1] = s1;
            }
        }
        // loop-top sync (1) guards mbuf/coef reuse
    }
}

// ---------------------------------------------------------------------------
// combine SPLITS partial softmax states per agent
// ---------------------------------------------------------------------------
__global__ __launch_bounds__(256) void k_combine(float* __restrict__ out) {
    int gw = (blockIdx.x * blockDim.x + threadIdx.x) >> 5;
    int lane = threadIdx.x & 31;
    if (gw >= A) return;
    int a = gw;
    float mm[SPLITS], llv[SPLITS];
    float M = -1e30f;
#pragma unroll
    for (int k = 0; k < SPLITS; k++) {
        mm[k] = g_pm[a * SPLITS + k];
        llv[k] = g_pl[a * SPLITS + k];
        M = fmaxf(M, mm[k]);
    }
    const float* gp = (const float*)g_paccu;
    float L = 0.f, v = 0.f;
#pragma unroll
    for (int k = 0; k < SPLITS; k++) {
        float sk = __expf(mm[k] - M);
        L += llv[k] * sk;
        v += gp[(size_t)(a * SPLITS + k) * C + lane] * sk;
    }
    out[a * C + lane] = v / L;
}

// ---------------------------------------------------------------------------
extern "C" void kernel_launch(void* const* d_in, const int* in_sizes, int n_in,
                              void* d_out, int out_size) {
    const float* gs   = (const float*)d_in[0];
    const int*   sidx = (const int*)d_in[1];
    const float* dyn  = (const float*)d_in[2];
    const float* Wsn  = (const float*)d_in[3];
    const float* bsn  = (const float*)d_in[4];
    const float* Wdf  = (const float*)d_in[5];
    const float* bdf  = (const float*)d_in[6];
    const float* wfc  = (const float*)d_in[7];
    float* out = (float*)d_out;

    cudaFuncSetAttribute(k_prep, cudaFuncAttributeMaxDynamicSharedMemorySize,
                         PREP_SMEM);
    k_prep<<<S + A / 32, 256, PREP_SMEM>>>(sidx, dyn, Wdf, bdf);

    cudaFuncSetAttribute(k_attn, cudaFuncAttributeMaxDynamicSharedMemorySize,
                         SMEM_ATTN);
    k_attn<<<S * SPLITS, 256, SMEM_ATTN>>>(gs, wfc, Wsn, bsn);

    k_combine<<<(A * 32) / 256, 256>>>(out);
}

// round 11
// speedup vs baseline: 1.2512x; 1.0216x over previous
#include <cuda_runtime.h>
#include <cstdint>

#define S 64
#define P 2048
#define C 32
#define A 2048
#define D 128
#define E 64
#define E2 32

#define SPLITS 16
#define PH (P / SPLITS)   // 128 pixels per block

typedef unsigned long long ull;

__device__ __forceinline__ ull pack2(float lo, float hi) {
    ull r; asm("mov.b64 %0,{%1,%2};" : "=l"(r) : "f"(lo), "f"(hi)); return r;
}
__device__ __forceinline__ void unpack2(ull v, float& lo, float& hi) {
    asm("mov.b64 {%0,%1},%2;" : "=f"(lo), "=f"(hi) : "l"(v));
}
__device__ __forceinline__ ull fma2(ull a, ull b, ull c) {
    ull d; asm("fma.rn.f32x2 %0,%1,%2,%3;" : "=l"(d) : "l"(a), "l"(b), "l"(c)); return d;
}
__device__ __forceinline__ ull add2(ull a, ull b) {
    ull d; asm("add.rn.f32x2 %0,%1,%2;" : "=l"(d) : "l"(a), "l"(b)); return d;
}
__device__ __forceinline__ ull mul2(ull a, ull b) {
    ull d; asm("mul.rn.f32x2 %0,%1,%2;" : "=l"(d) : "l"(a), "l"(b)); return d;
}
__device__ __forceinline__ ull relu2(ull v) {
    float lo, hi; unpack2(v, lo, hi);
    return pack2(fmaxf(lo, 0.f), fmaxf(hi, 0.f));
}

// ------------------------- global scratch -------------------------
__device__ ull   g_att2u[A * E2];
__device__ int   g_alist[S * A];
__device__ int   g_cnt[S];
__device__ float g_pm[A * SPLITS];
__device__ float g_pl[A * SPLITS];
__device__ ull   g_paccu[A * SPLITS * (C / 2)];

// ---------------------------------------------------------------------------
// k_prep: blocks [0,S): per-scene agent lists (2-sync ballot compaction).
//         blocks [S, S+A/32): att2 for 32 agents.
// ---------------------------------------------------------------------------
#define PREP_SMEM 49152
__global__ __launch_bounds__(256) void k_prep(const int* __restrict__ sidx,
                                              const float* __restrict__ dyn,
                                              const float* __restrict__ Wdf,
                                              const float* __restrict__ bdf) {
    extern __shared__ __align__(16) char dsm[];
    __shared__ int cnt8[64];   // [round][warp]

    const int tid = threadIdx.x, wid = tid >> 5, lane = tid & 31;

    if (blockIdx.x < S) {
        // ---- group role ----
        const int s = blockIdx.x;
        unsigned pm = 0;
        int rank[8];
#pragma unroll
        for (int r = 0; r < 8; r++) {
            int a = r * 256 + tid;
            bool p = (sidx[a] == s);
            unsigned bal = __ballot_sync(0xffffffffu, p);
            if (lane == 0) cnt8[r * 8 + wid] = __popc(bal);
            if (p) pm |= (1u << r);
            rank[r] = __popc(bal & ((1u << lane) - 1u));
        }
        __syncthreads();
        int run = 0, off[8];
#pragma unroll
        for (int r = 0; r < 8; r++) {
            int woff = 0, tot = 0;
#pragma unroll
            for (int w = 0; w < 8; w++) {
                int c = cnt8[r * 8 + w];
                if (w < wid) woff += c;
                tot += c;
            }
            off[r] = run + woff;
            run += tot;
        }
#pragma unroll
        for (int r = 0; r < 8; r++)
            if ((pm >> r) & 1)
                g_alist[s * A + off[r] + rank[r]] = r * 256 + tid;
        if (tid == 0) g_cnt[s] = run;
        return;
    }

    // ---- att2 role: 32 agents, 4 per warp ----
    ull*   Wp2   = (ull*)dsm;                 // [128][32] = 32 KB
    float* dyn_s = (float*)(dsm + 32768);     // [32][128] = 16 KB
    const int a0 = (blockIdx.x - S) * 32;
    {
        const ull* Wsrc = (const ull*)Wdf;
#pragma unroll
        for (int k = 0; k < 16; k++) Wp2[tid + k * 256] = Wsrc[tid + k * 256];
        const float4* dsrc = (const float4*)(dyn + (size_t)a0 * D);
        float4* ddst = (float4*)dyn_s;
#pragma unroll
        for (int k = 0; k < 4; k++) ddst[tid + k * 256] = dsrc[tid + k * 256];
    }
    __syncthreads();

    ull acc[4];
    ull b0 = ((const ull*)bdf)[lane];
#pragma unroll
    for (int i = 0; i < 4; i++) acc[i] = b0;
    const float* dr = dyn_s + (wid * 4) * D;
#pragma unroll 4
    for (int c = 0; c < D; c++) {
        ull w2 = Wp2[c * 32 + lane];
#pragma unroll
        for (int i = 0; i < 4; i++) {
            float d = dr[i * D + c];
            acc[i] = fma2(pack2(d, d), w2, acc[i]);
        }
    }
#pragma unroll
    for (int i = 0; i < 4; i++)
        g_att2u[(size_t)(a0 + wid * 4 + i) * E2 + lane] = acc[i];
}

// ---------------------------------------------------------------------------
// k_attn — block = (scene, part). 256 threads / 8 warps, 3 blocks/SM.
// lane = agent (32-agent chunks), warp = 16-pixel slice of 128 pixels.
// Merge buffer overlays Wp+att2T (dead after prologue / logit phase).
// b_fc dropped (softmax-invariant).
// ---------------------------------------------------------------------------
// smem layout (bytes)
#define OFF_ATT1S 0                   // ull[128*34] = 34816
#define OFF_GSS   34816               // ull[128*16] = 16384
#define OFF_OVR   51200               // overlay region, 17408 bytes:
                                      //   Wp    @ +0     (ull[32*32] = 8192)
                                      //   att2T @ +8192  (ull[32*33] = 8448)
                                      //   mbuf  @ +0     (ull[4*17*32] = 17408)
#define OFF_COEF  68608               // float[4*32] = 512
#define OFF_WFC   69120               // ull[32] = 256
#define OFF_BSN   69376               // ull[32] = 256
#define SMEM_ATTN 69632

__global__ __launch_bounds__(256, 3) void k_attn(const float* __restrict__ gs,
                                                 const float* __restrict__ wfc,
                                                 const float* __restrict__ Wsn,
                                                 const float* __restrict__ bsn) {
    extern __shared__ __align__(16) char smraw[];
    ull*   att1s = (ull*)(smraw + OFF_ATT1S);        // [px][34]
    ull*   gss   = (ull*)(smraw + OFF_GSS);          // [px][16]
    ull*   Wp    = (ull*)(smraw + OFF_OVR);          // [c][32] (prologue only)
    ull*   att2T = (ull*)(smraw + OFF_OVR + 8192);   // [e2][33] (logit phase)
    ull*   mbuf  = (ull*)(smraw + OFF_OVR);          // [4][17][32] (merge phase)
    float* coef  = (float*)(smraw + OFF_COEF);       // [4][32]
    ull*   wfcp  = (ull*)(smraw + OFF_WFC);
    ull*   bsnp  = (ull*)(smraw + OFF_BSN);

    const int tid = threadIdx.x, wid = tid >> 5, lane = tid & 31;
    const int sblk = blockIdx.x & 63;     // part-major: waves mix scenes
    const int part = blockIdx.x >> 6;
    const int p0 = part * PH;
    const int nA = g_cnt[sblk];
    if (nA == 0) return;

    const int* alist = g_alist + sblk * A;

    // ---- stage weights ----
    {
        const ull* Wsrc = (const ull*)Wsn;
        for (int i = tid; i < C * E2; i += 256) Wp[i] = Wsrc[i];
        if (tid < E2) {
            wfcp[tid] = ((const ull*)wfc)[tid];
            bsnp[tid] = ((const ull*)bsn)[tid];
        }
    }
    __syncthreads();

    // ---- prologue: gs loads in flight, chunk-0 att2 staging, att1 compute --
    {
        const int px = tid >> 1, h16 = (tid & 1) * 16;
        const float4* gr = (const float4*)(gs + (size_t)(sblk * P + p0 + px) * C);
        float4 v4[8];
#pragma unroll
        for (int j = 0; j < 8; j++) v4[j] = gr[j];

        // chunk-0 att2 staging (LDG latency overlaps the compute below)
        for (int idx = tid; idx < 32 * E2; idx += 256) {
            int j = idx >> 5, e2 = idx & 31;
            int src = j; if (src >= nA) src = nA - 1;
            att2T[e2 * 33 + j] = g_att2u[(size_t)alist[src] * E2 + e2];
        }

        if ((tid & 1) == 0) {
            float4* gd = (float4*)(gss + px * 16);
#pragma unroll
            for (int j = 0; j < 8; j++) gd[j] = v4[j];
        }
        ull acc[16];
#pragma unroll
        for (int k = 0; k < 16; k++) acc[k] = bsnp[h16 + k];
#pragma unroll
        for (int j = 0; j < 8; j++) {
            const float4 v = v4[j];
            {
                ull gg = pack2(v.x, v.x);
                const ull* wr = Wp + (4 * j + 0) * E2 + h16;
#pragma unroll
                for (int k = 0; k < 16; k++) acc[k] = fma2(gg, wr[k], acc[k]);
            }
            {
                ull gg = pack2(v.y, v.y);
                const ull* wr = Wp + (4 * j + 1) * E2 + h16;
#pragma unroll
                for (int k = 0; k < 16; k++) acc[k] = fma2(gg, wr[k], acc[k]);
            }
            {
                ull gg = pack2(v.z, v.z);
                const ull* wr = Wp + (4 * j + 2) * E2 + h16;
#pragma unroll
                for (int k = 0; k < 16; k++) acc[k] = fma2(gg, wr[k], acc[k]);
            }
            {
                ull gg = pack2(v.w, v.w);
                const ull* wr = Wp + (4 * j + 3) * E2 + h16;
#pragma unroll
                for (int k = 0; k < 16; k++) acc[k] = fma2(gg, wr[k], acc[k]);
            }
        }
        ulonglong2* dst = (ulonglong2*)(att1s + px * 34 + h16);
#pragma unroll
        for (int k = 0; k < 8; k++) {
            ulonglong2 v2; v2.x = acc[2 * k]; v2.y = acc[2 * k + 1];
            dst[k] = v2;
        }
    }
    __syncthreads();   // att1s, gss, att2T(chunk 0) visible

    const int pbase = wid * 16;

    for (int c0 = 0; c0 < nA; c0 += 32) {
        // ---- logits: 16 pixels x 32 lane-agents (att2T already staged) ----
        ull lg[16];
#pragma unroll
        for (int i = 0; i < 16; i++) lg[i] = 0ull;
#pragma unroll 2
        for (int e2 = 0; e2 < E2; e2 += 2) {
            ull wv0 = wfcp[e2], wv1 = wfcp[e2 + 1];
            ull bv0 = att2T[e2 * 33 + lane], bv1 = att2T[(e2 + 1) * 33 + lane];
            const ulonglong2* a1 = (const ulonglong2*)(att1s + pbase * 34 + e2);
#pragma unroll
            for (int i = 0; i < 16; i++) {
                ulonglong2 av = a1[i * 17];
                lg[i] = fma2(relu2(add2(av.x, bv0)), wv0, lg[i]);
                lg[i] = fma2(relu2(add2(av.y, bv1)), wv1, lg[i]);
            }
        }
        // ---- single-shot softmax over this warp's 16 pixels ----
        float ls[16];
#pragma unroll
        for (int i = 0; i < 16; i++) {
            float lo, hi; unpack2(lg[i], lo, hi);
            ls[i] = lo + hi;
        }
        float t8[8];
#pragma unroll
        for (int i = 0; i < 8; i++) t8[i] = fmaxf(ls[i], ls[i + 8]);
        float m = fmaxf(fmaxf(fmaxf(t8[0], t8[4]), fmaxf(t8[1], t8[5])),
                        fmaxf(fmaxf(t8[2], t8[6]), fmaxf(t8[3], t8[7])));
        float l0 = 0.f, l1 = 0.f;
        ull acc[16];
#pragma unroll
        for (int k = 0; k < 16; k++) acc[k] = 0ull;
#pragma unroll 4
        for (int i = 0; i < 16; i++) {
            float w = __expf(ls[i] - m);
            if (i & 1) l1 += w; else l0 += w;
            ull w2 = pack2(w, w);
            const ulonglong2* grw = (const ulonglong2*)(gss + (pbase + i) * 16);
#pragma unroll
            for (int k = 0; k < 8; k++) {
                ulonglong2 gv = grw[k];
                acc[2 * k]     = fma2(w2, gv.x, acc[2 * k]);
                acc[2 * k + 1] = fma2(w2, gv.y, acc[2 * k + 1]);
            }
        }
        float l = l0 + l1;

        __syncthreads();   // (B) logit/V done -> overlay region reusable

        // ---- warps 4-7 dump into slots 0-3 ----
        if (wid >= 4) {
            ull* dst = mbuf + (size_t)(wid - 4) * 17 * 32;
#pragma unroll
            for (int k = 0; k < 16; k++) dst[k * 32 + lane] = acc[k];
            dst[16 * 32 + lane] = pack2(m, l);
        }
        __syncthreads();   // (C)

        // ---- warps 0-3: fold partner state into registers, write back ----
        if (wid < 4) {
            ull* sl = mbuf + (size_t)wid * 17 * 32;
            float m2, l2; unpack2(sl[16 * 32 + lane], m2, l2);
            float Mn = fmaxf(m, m2);
            float s1 = __expf(m - Mn), s2 = __expf(m2 - Mn);
            l = l * s1 + l2 * s2;
            ull s1v = pack2(s1, s1), s2v = pack2(s2, s2);
#pragma unroll
            for (int k = 0; k < 16; k++) {
                acc[k] = fma2(sl[k * 32 + lane], s2v, mul2(acc[k], s1v));
                sl[k * 32 + lane] = acc[k];
            }
            sl[16 * 32 + lane] = pack2(Mn, l);
        }
        __syncthreads();   // (D)

        const int aidx = c0 + lane;
        const bool valid = (aidx < nA);

        if (wid == 0) {
            float mj[4], lj[4];
#pragma unroll
            for (int j = 0; j < 4; j++)
                unpack2(mbuf[(size_t)j * 17 * 32 + 16 * 32 + lane], mj[j], lj[j]);
            float M = fmaxf(fmaxf(mj[0], mj[1]), fmaxf(mj[2], mj[3]));
            float L = 0.f;
#pragma unroll
            for (int j = 0; j < 4; j++) {
                float cj = __expf(mj[j] - M);
                coef[j * 32 + lane] = cj;
                L += lj[j] * cj;
            }
            if (valid) {
                int a = alist[aidx];
                g_pm[(size_t)a * SPLITS + part] = M;
                g_pl[(size_t)a * SPLITS + part] = L;
            }
        }
        __syncthreads();   // (E) coefs visible

        // ---- all 8 warps: weighted k-sums over 4 merged states ----
        {
            const int k0 = wid * 2;
            ull s0 = 0ull, s1 = 0ull;
#pragma unroll
            for (int j = 0; j < 4; j++) {
                float cj = coef[j * 32 + lane];
                ull c2 = pack2(cj, cj);
                const ull* src = mbuf + (size_t)j * 17 * 32;
                s0 = fma2(src[k0 * 32 + lane], c2, s0);
                s1 = fma2(src[(k0 + 1) * 32 + lane], c2, s1);
            }
            if (valid) {
                int a = alist[aidx];
                size_t base = ((size_t)a * SPLITS + part) * 16;
                g_paccu[base + k0] = s0;
                g_paccu[base + k0 + 1] = s1;
            }
        }

        // ---- stage next chunk's att2 (rare) ----
        if (c0 + 32 < nA) {
            __syncthreads();   // ksum readers done with mbuf
            for (int idx = tid; idx < 32 * E2; idx += 256) {
                int j = idx >> 5, e2 = idx & 31;
                int src = c0 + 32 + j; if (src >= nA) src = nA - 1;
                att2T[e2 * 33 + j] = g_att2u[(size_t)alist[src] * E2 + e2];
            }
            __syncthreads();   // att2T visible for next iteration
        }
    }
}

// ---------------------------------------------------------------------------
// combine SPLITS partial softmax states per agent
// ---------------------------------------------------------------------------
__global__ __launch_bounds__(256) void k_combine(float* __restrict__ out) {
    int gw = (blockIdx.x * blockDim.x + threadIdx.x) >> 5;
    int lane = threadIdx.x & 31;
    if (gw >= A) return;
    int a = gw;
    float mm[SPLITS], llv[SPLITS];
    float M = -1e30f;
#pragma unroll
    for (int k = 0; k < SPLITS; k++) {
        mm[k] = g_pm[a * SPLITS + k];
        llv[k] = g_pl[a * SPLITS + k];
        M = fmaxf(M, mm[k]);
    }
    const float* gp = (const float*)g_paccu;
    float L = 0.f, v = 0.f;
#pragma unroll
    for (int k = 0; k < SPLITS; k++) {
        float sk = __expf(mm[k] - M);
        L += llv[k] * sk;
        v += gp[(size_t)(a * SPLITS + k) * C + lane] * sk;
    }
    out[a * C + lane] = v / L;
}

// ---------------------------------------------------------------------------
extern "C" void kernel_launch(void* const* d_in, const int* in_sizes, int n_in,
                              void* d_out, int out_size) {
    const float* gs   = (const float*)d_in[0];
    const int*   sidx = (const int*)d_in[1];
    const float* dyn  = (const float*)d_in[2];
    const float* Wsn  = (const float*)d_in[3];
    const float* bsn  = (const float*)d_in[4];
    const float* Wdf  = (const float*)d_in[5];
    const float* bdf  = (const float*)d_in[6];
    const float* wfc  = (const float*)d_in[7];
    float* out = (float*)d_out;

    cudaFuncSetAttribute(k_prep, cudaFuncAttributeMaxDynamicSharedMemorySize,
                         PREP_SMEM);
    k_prep<<<S + A / 32, 256, PREP_SMEM>>>(sidx, dyn, Wdf, bdf);

    cudaFuncSetAttribute(k_attn, cudaFuncAttributeMaxDynamicSharedMemorySize,
                         SMEM_ATTN);
    k_attn<<<S * SPLITS, 256, SMEM_ATTN>>>(gs, wfc, Wsn, bsn);

    k_combine<<<(A * 32) / 256, 256>>>(out);
}